// round 10
// baseline (speedup 1.0000x reference)
#include <cuda_runtime.h>

#define BATCH 2
#define NCAM  6
#define CH    128
#define IH    16
#define IW    44
#define ND    64
#define HW    (IH*IW)                 // 704
#define NPTS  (NCAM*ND*IH*IW)         // 270336 geometry points (batch-independent)
#define BEV_H 256
#define BEV_W 256
#define NBIN  (BEV_H*BEV_W)           // 65536
#define NTILE (NBIN/32)               // 2048
#define CAMSTRIDE (NCAM*ND*HW)        // depth elements per batch
#define B1OFF  (NCAM*HW*CH)           // featT offset of batch 1

#define PT_BLOCKS   (NPTS/256)        // 1056
#define TR_BLOCKS   ((CH/32)*(HW/32)*BATCH*NCAM)  // 1056
#define FILL_BLOCKS (NPTS/1024)       // 264

#define CAP    32                     // points handled in-tile per bin
#define HCHUNK 64                     // hot remainder chunk length
#define MAXHC  16384                  // hot chunk list capacity
#define HOTBLK 256                    // gatherHot grid (2048 warps)

typedef unsigned long long ull;

// Static scratch (allocation-free per harness rules)
__device__ float g_featT[(size_t)BATCH*NCAM*HW*CH];  // feat channel-last: (bn, hw, c)
__device__ int   g_bin[NPTS];                        // bin index or -1
__device__ __align__(16) int g_cnt_i[NBIN];          // per-bin count (re-zeroed each run)
__device__ __align__(16) int g_off[NBIN+1];          // CSR offsets (exclusive)
__device__ __align__(16) int g_wptr[NBIN];           // write cursors for fill
__device__ int   g_bsum[64];
__device__ volatile int g_flag[64];                  // scan publish flags (re-zeroed each run)
__device__ int   g_sched[NTILE];                     // tile schedule, hot first
__device__ __align__(16) float4 g_list[NPTS];        // {fpix*CH as int, pad, d0, d1}
__device__ int   g_hc_bin[MAXHC];                    // hot chunk: bin
__device__ int   g_hc_beg[MAXHC];                    // hot chunk: start in list
__device__ int   g_hc_len[MAXHC];                    // hot chunk: length
__device__ int   g_nhc;                              // number of hot chunks

// ---------------------------------------------------------------------------
// In-block camera setup (geometry identical across batch; b=0 slices).
// ---------------------------------------------------------------------------
__device__ __forceinline__ void cam_setup(const float* __restrict__ intr,
                                          const float* __restrict__ extr,
                                          const int* __restrict__ pimg_h,
                                          const int* __restrict__ pimg_w,
                                          float* sKi, float* sRm, float* stv) {
    int n = threadIdx.x;
    if (n < NCAM) {
        float img_h = (float)pimg_h[0], img_w = (float)pimg_w[0];
        float sx = (float)IW / (img_w / 16.0f);
        float sy = (float)IH / (img_h / 16.0f);
        float rs0 = 16.0f / sx, rs1 = 16.0f / sy, rs2 = 1.0f;

        const float* Kp = intr + n*9;
        float a = Kp[0]*rs0, b = Kp[1]*rs0, c = Kp[2]*rs0;
        float d = Kp[3]*rs1, e = Kp[4]*rs1, f = Kp[5]*rs1;
        float g = Kp[6]*rs2, h = Kp[7]*rs2, i = Kp[8]*rs2;
        float A  = e*i - f*h;
        float Bc = -(d*i - f*g);
        float Cc = d*h - e*g;
        float det = a*A + b*Bc + c*Cc;
        float id = 1.0f / det;
        float* Ki = sKi + n*9;
        Ki[0] = A*id;             Ki[1] = (c*h - b*i)*id;  Ki[2] = (b*f - c*e)*id;
        Ki[3] = Bc*id;            Ki[4] = (a*i - c*g)*id;  Ki[5] = (c*d - a*f)*id;
        Ki[6] = Cc*id;            Ki[7] = (b*g - a*h)*id;  Ki[8] = (a*e - b*d)*id;

        const float* Ep = extr + n*16;
        #pragma unroll
        for (int r = 0; r < 3; r++) {
            #pragma unroll
            for (int cc = 0; cc < 3; cc++) sRm[n*9 + r*3+cc] = Ep[r*4+cc];
            stv[n*3 + r] = Ep[r*4+3];
        }
    }
}

// ---------------------------------------------------------------------------
// Fused kernel A: blocks [0, PT_BLOCKS) -> point geometry (bin + count);
// blocks [PT_BLOCKS, ...) -> feat transpose to channel-last.
// ---------------------------------------------------------------------------
__global__ void __launch_bounds__(256) pointA_kernel(
        const float* __restrict__ feat,
        const float* __restrict__ intr, const float* __restrict__ extr,
        const int* __restrict__ pimg_h, const int* __restrict__ pimg_w) {
    if (blockIdx.x < PT_BLOCKS) {
        __shared__ float sKi[NCAM*9], sRm[NCAM*9], stv[NCAM*3];
        cam_setup(intr, extr, pimg_h, pimg_w, sKi, sRm, stv);
        __syncthreads();

        int wp = blockIdx.x * 256 + threadIdx.x;
        int w   = wp % IW;  int t = wp / IW;
        int h   = t % IH;   t /= IH;
        int dci = t % ND;
        int n   = t / ND;

        float dd = 1.0f + (59.0f / 63.0f) * (float)dci;  // linspace(1,60,64)
        float ux = (float)w * dd;
        float vy = (float)h * dd;

        const float* Ki = sKi + n*9;
        float pcx = Ki[0]*ux + Ki[1]*vy + Ki[2]*dd;
        float pcy = Ki[3]*ux + Ki[4]*vy + Ki[5]*dd;
        float pcz = Ki[6]*ux + Ki[7]*vy + Ki[8]*dd;

        const float* Rm = sRm + n*9;
        const float* tv = stv + n*3;
        float px = Rm[0]*pcx + Rm[1]*pcy + Rm[2]*pcz + tv[0];
        float py = Rm[3]*pcx + Rm[4]*pcy + Rm[5]*pcz + tv[1];
        float pz = Rm[6]*pcx + Rm[7]*pcy + Rm[8]*pcz + tv[2];

        int xi = (int)__fdiv_rn(px - (-51.2f), 0.4f);
        int yi = (int)__fdiv_rn(py - (-51.2f), 0.4f);
        bool valid = (xi >= 0) & (xi < BEV_W) & (yi >= 0) & (yi < BEV_H)
                   & (pz >= -5.0f) & (pz <= 3.0f);

        int bin = yi * BEV_W + xi;
        g_bin[wp] = valid ? bin : -1;
        if (valid) atomicAdd(&g_cnt_i[bin], 1);
    } else {
        __shared__ float tile[32][33];
        int tb  = blockIdx.x - PT_BLOCKS;
        int c0  = (tb & 3) * 32;          // CH/32 = 4
        int hw0 = ((tb >> 2) % 22) * 32;  // HW/32 = 22
        int bn  = tb / 88;
        int x = threadIdx.x & 31, y = threadIdx.x >> 5;
        const float* src = feat + (size_t)bn * CH * HW;
        #pragma unroll
        for (int k = 0; k < 4; k++)
            tile[y + k*8][x] = src[(size_t)(c0 + y + k*8) * HW + hw0 + x];
        __syncthreads();
        #pragma unroll
        for (int k = 0; k < 4; k++)
            g_featT[((size_t)bn * HW + hw0 + y + k*8) * CH + c0 + x] = tile[x][y + k*8];
    }
}

// ---------------------------------------------------------------------------
// Single-kernel scan: 64 blocks x 256 threads x int4 (all co-resident).
// ---------------------------------------------------------------------------
__global__ void __launch_bounds__(256) scan_kernel() {
    __shared__ int wsum[8], wexcl[8], sexcl[64];
    int t   = threadIdx.x;
    int bid = blockIdx.x;
    int gb  = bid * 1024 + t * 4;
    int4 c = *(const int4*)&g_cnt_i[gb];
    int s = c.x + c.y + c.z + c.w;
    int lane = t & 31, wid = t >> 5;
    int incl = s;
    #pragma unroll
    for (int d = 1; d < 32; d <<= 1) {
        int v = __shfl_up_sync(0xffffffffu, incl, d);
        if (lane >= d) incl += v;
    }
    if (lane == 31) wsum[wid] = incl;
    __syncthreads();
    if (t < 8) {
        int v = wsum[t];
        int iv = v;
        #pragma unroll
        for (int d = 1; d < 8; d <<= 1) {
            int u = __shfl_up_sync(0xffu, iv, d);
            if (t >= d) iv += u;
        }
        wexcl[t] = iv - v;
    }
    __syncthreads();
    int excl = incl - s + wexcl[wid];
    if (t == 255) {
        g_bsum[bid] = excl + s;
        __threadfence();
        g_flag[bid] = 1;
    }

    if (t < 64) {
        while (g_flag[t] == 0) { }
    }
    __syncthreads();
    __threadfence();
    if (t < 64) {
        int v = g_bsum[t];
        int iv = v;
        int l = t & 31;
        #pragma unroll
        for (int d = 1; d < 32; d <<= 1) {
            int u = __shfl_up_sync(0xffffffffu, iv, d);
            if (l >= d) iv += u;
        }
        if (t == 31) wsum[0] = iv;
        __syncwarp();
        sexcl[t] = iv - v;
    }
    __syncthreads();
    int base = sexcl[bid] + ((bid >= 32) ? wsum[0] : 0);
    int4 o;
    o.x = base + excl; o.y = o.x + c.x; o.z = o.y + c.y; o.w = o.z + c.z;
    *(int4*)&g_off[gb]  = o;
    *(int4*)&g_wptr[gb] = o;
    if (bid == 63 && t == 255) g_off[NBIN] = o.w + c.w;
}

// ---------------------------------------------------------------------------
// Fused kernel B: fill fat list entries {fpix*CH, pad, d0, d1} with warp-
// aggregated cursor atomics; extra block builds hot-first schedule + global
// hot-chunk list and re-zeroes g_cnt_i / g_flag for replay (coalesced).
// ---------------------------------------------------------------------------
__global__ void __launch_bounds__(1024) fillB_kernel(const float* __restrict__ depth) {
    int t = threadIdx.x;
    if (blockIdx.x < FILL_BLOCKS) {
        int wp = blockIdx.x * 1024 + t;
        int bin = g_bin[wp];
        int lane = t & 31;

        // warp-aggregate cursor atomics by bin (hot bins: 32 atomics -> 1)
        unsigned mask = __match_any_sync(0xffffffffu, bin);
        if (bin >= 0) {
            int leader = __ffs(mask) - 1;
            int rank = __popc(mask & ((1u << lane) - 1u));
            int pos0 = 0;
            if (lane == leader) pos0 = atomicAdd(&g_wptr[bin], __popc(mask));
            pos0 = __shfl_sync(mask, pos0, leader);

            int w   = wp % IW;  int q = wp / IW;
            int h   = q % IH;   q /= IH;
            int dci = q % ND;
            int n   = q / ND;
            int hw  = h * IW + w;
            int dpo = (n * ND + dci) * HW + hw;

            float4 e;
            e.x = __int_as_float((n * HW + hw) * CH);
            e.y = 0.f;
            e.z = __ldg(&depth[dpo]);
            e.w = __ldg(&depth[CAMSTRIDE + dpo]);
            g_list[pos0 + rank] = e;
        }
    } else {
        // coalesced re-zero of counts + flags for next replay
        int4 z = {0, 0, 0, 0};
        #pragma unroll
        for (int j = 0; j < 16; j++)
            *(int4*)&g_cnt_i[(j * 1024 + t) * 4] = z;
        if (t < 64) *(int*)&g_flag[t] = 0;

        // hot-first schedule over 2048 tiles
        __shared__ int bcnt[8], bbase[8], hbase;
        if (t < 8) bcnt[t] = 0;
        if (t == 0) hbase = 0;
        __syncthreads();
        int ks[2];
        #pragma unroll
        for (int j = 0; j < 2; j++) {
            int tile = t + j * 1024;
            int cnt = g_off[tile*32 + 32] - g_off[tile*32];
            int k = cnt > 4096 ? 0 : cnt > 2048 ? 1 : cnt > 1024 ? 2 : cnt > 512 ? 3 :
                    cnt > 256  ? 4 : cnt > 128  ? 5 : cnt > 64   ? 6 : 7;
            ks[j] = k;
            atomicAdd(&bcnt[k], 1);
        }
        __syncthreads();
        if (t == 0) {
            int r = 0;
            #pragma unroll
            for (int k = 0; k < 8; k++) { bbase[k] = r; r += bcnt[k]; }
        }
        __syncthreads();
        #pragma unroll
        for (int j = 0; j < 2; j++) {
            int pos = atomicAdd(&bbase[ks[j]], 1);
            g_sched[pos] = t + j * 1024;
        }

        // global hot-chunk list: remainder beyond CAP, chunks of HCHUNK.
        // coalesced traversal: bin = j*1024 + t.
        #pragma unroll
        for (int j = 0; j < 64; j++) {
            int bin = j * 1024 + t;
            int beg = g_off[bin];
            int cnt = g_off[bin + 1] - beg;
            if (cnt > CAP) {
                int rem = cnt - CAP;
                int nch = (rem + HCHUNK - 1) / HCHUNK;
                int pos = atomicAdd(&hbase, nch);
                for (int k = 0; k < nch; k++) {
                    int p = pos + k;
                    if (p < MAXHC) {
                        g_hc_bin[p] = bin;
                        g_hc_beg[p] = beg + CAP + k * HCHUNK;
                        int l = rem - k * HCHUNK; if (l > HCHUNK) l = HCHUNK;
                        g_hc_len[p] = l;
                    }
                }
            }
        }
        __syncthreads();
        if (t == 0) g_nhc = hbase < MAXHC ? hbase : MAXHC;
    }
}

// ---------------------------------------------------------------------------
// Inner accumulate: QUAD-pipelined (4 list loads, then 8 feat loads, 16 FMA2).
// ---------------------------------------------------------------------------
__device__ __forceinline__ void fma_one(float4 e, int lane,
        ull& a0x, ull& a0y, ull& a1x, ull& a1y) {
    int foff = __float_as_int(e.x);
    ull d0p, d1p;
    asm("mov.b64 %0, {%1, %1};" : "=l"(d0p) : "f"(e.z));
    asm("mov.b64 %0, {%1, %1};" : "=l"(d1p) : "f"(e.w));
    ulonglong2 v0 = *((const ulonglong2*)(g_featT + foff) + lane);
    ulonglong2 v1 = *((const ulonglong2*)(g_featT + (B1OFF + foff)) + lane);
    asm("fma.rn.f32x2 %0, %1, %2, %0;" : "+l"(a0x) : "l"(v0.x), "l"(d0p));
    asm("fma.rn.f32x2 %0, %1, %2, %0;" : "+l"(a0y) : "l"(v0.y), "l"(d0p));
    asm("fma.rn.f32x2 %0, %1, %2, %0;" : "+l"(a1x) : "l"(v1.x), "l"(d1p));
    asm("fma.rn.f32x2 %0, %1, %2, %0;" : "+l"(a1y) : "l"(v1.y), "l"(d1p));
}

__device__ __forceinline__ void accum_run(int beg, int end, int lane,
        ull& a0x, ull& a0y, ull& a1x, ull& a1y) {
    int i = beg;
    for (; i + 4 <= end; i += 4) {
        float4 e0 = __ldg(&g_list[i+0]);
        float4 e1 = __ldg(&g_list[i+1]);
        float4 e2 = __ldg(&g_list[i+2]);
        float4 e3 = __ldg(&g_list[i+3]);
        const float* p0 = g_featT + __float_as_int(e0.x);
        const float* p1 = g_featT + __float_as_int(e1.x);
        const float* p2 = g_featT + __float_as_int(e2.x);
        const float* p3 = g_featT + __float_as_int(e3.x);
        ulonglong2 v00 = *((const ulonglong2*)p0 + lane);
        ulonglong2 v10 = *((const ulonglong2*)(p0 + B1OFF) + lane);
        ulonglong2 v01 = *((const ulonglong2*)p1 + lane);
        ulonglong2 v11 = *((const ulonglong2*)(p1 + B1OFF) + lane);
        ulonglong2 v02 = *((const ulonglong2*)p2 + lane);
        ulonglong2 v12 = *((const ulonglong2*)(p2 + B1OFF) + lane);
        ulonglong2 v03 = *((const ulonglong2*)p3 + lane);
        ulonglong2 v13 = *((const ulonglong2*)(p3 + B1OFF) + lane);
        ull d00, d10, d01, d11, d02, d12, d03, d13;
        asm("mov.b64 %0, {%1, %1};" : "=l"(d00) : "f"(e0.z));
        asm("mov.b64 %0, {%1, %1};" : "=l"(d10) : "f"(e0.w));
        asm("mov.b64 %0, {%1, %1};" : "=l"(d01) : "f"(e1.z));
        asm("mov.b64 %0, {%1, %1};" : "=l"(d11) : "f"(e1.w));
        asm("mov.b64 %0, {%1, %1};" : "=l"(d02) : "f"(e2.z));
        asm("mov.b64 %0, {%1, %1};" : "=l"(d12) : "f"(e2.w));
        asm("mov.b64 %0, {%1, %1};" : "=l"(d03) : "f"(e3.z));
        asm("mov.b64 %0, {%1, %1};" : "=l"(d13) : "f"(e3.w));
        asm("fma.rn.f32x2 %0, %1, %2, %0;" : "+l"(a0x) : "l"(v00.x), "l"(d00));
        asm("fma.rn.f32x2 %0, %1, %2, %0;" : "+l"(a0y) : "l"(v00.y), "l"(d00));
        asm("fma.rn.f32x2 %0, %1, %2, %0;" : "+l"(a1x) : "l"(v10.x), "l"(d10));
        asm("fma.rn.f32x2 %0, %1, %2, %0;" : "+l"(a1y) : "l"(v10.y), "l"(d10));
        asm("fma.rn.f32x2 %0, %1, %2, %0;" : "+l"(a0x) : "l"(v01.x), "l"(d01));
        asm("fma.rn.f32x2 %0, %1, %2, %0;" : "+l"(a0y) : "l"(v01.y), "l"(d01));
        asm("fma.rn.f32x2 %0, %1, %2, %0;" : "+l"(a1x) : "l"(v11.x), "l"(d11));
        asm("fma.rn.f32x2 %0, %1, %2, %0;" : "+l"(a1y) : "l"(v11.y), "l"(d11));
        asm("fma.rn.f32x2 %0, %1, %2, %0;" : "+l"(a0x) : "l"(v02.x), "l"(d02));
        asm("fma.rn.f32x2 %0, %1, %2, %0;" : "+l"(a0y) : "l"(v02.y), "l"(d02));
        asm("fma.rn.f32x2 %0, %1, %2, %0;" : "+l"(a1x) : "l"(v12.x), "l"(d12));
        asm("fma.rn.f32x2 %0, %1, %2, %0;" : "+l"(a1y) : "l"(v12.y), "l"(d12));
        asm("fma.rn.f32x2 %0, %1, %2, %0;" : "+l"(a0x) : "l"(v03.x), "l"(d03));
        asm("fma.rn.f32x2 %0, %1, %2, %0;" : "+l"(a0y) : "l"(v03.y), "l"(d03));
        asm("fma.rn.f32x2 %0, %1, %2, %0;" : "+l"(a1x) : "l"(v13.x), "l"(d13));
        asm("fma.rn.f32x2 %0, %1, %2, %0;" : "+l"(a1y) : "l"(v13.y), "l"(d13));
    }
    for (; i < end; i++) {
        float4 e = __ldg(&g_list[i]);
        fma_one(e, lane, a0x, a0y, a1x, a1y);
    }
}

__device__ __forceinline__ void unpack8(ull a0x, ull a0y, ull a1x, ull a1y,
        float& f0, float& f1, float& f2, float& f3,
        float& f4, float& f5, float& f6, float& f7) {
    asm("mov.b64 {%0, %1}, %2;" : "=f"(f0), "=f"(f1) : "l"(a0x));
    asm("mov.b64 {%0, %1}, %2;" : "=f"(f2), "=f"(f3) : "l"(a0y));
    asm("mov.b64 {%0, %1}, %2;" : "=f"(f4), "=f"(f5) : "l"(a1x));
    asm("mov.b64 {%0, %1}, %2;" : "=f"(f6), "=f"(f7) : "l"(a1y));
}

// ---------------------------------------------------------------------------
// gatherMain: block = 32-bin tile, 8 warps, warp owns 4 bins. Each bin:
// first <=CAP points only, plain smem stores, bounded per-block work.
// Epilogue plain-stores EVERY output element (hot bins: scaled partial,
// which initializes the poisoned out; gatherHot adds the rest after).
// ---------------------------------------------------------------------------
__global__ void __launch_bounds__(256) gatherMain_kernel(float* __restrict__ out) {
    __shared__ float acc[BATCH][32][CH + 1];
    __shared__ float sinv[32];

    int tile = g_sched[blockIdx.x];
    int bin0 = tile * 32;
    int tid  = threadIdx.x;
    int warp = tid >> 5;
    int lane = tid & 31;

    #pragma unroll
    for (int bl = warp; bl < 32; bl += 8) {
        int bin = bin0 + bl;
        int beg = g_off[bin];
        int end = g_off[bin + 1];
        int cnt = end - beg;
        if (lane == 0) sinv[bl] = __fdiv_rn(1.0f, (float)cnt + 1e-5f);

        int p1 = cnt < CAP ? cnt : CAP;
        ull a0x = 0, a0y = 0, a1x = 0, a1y = 0;
        accum_run(beg, beg + p1, lane, a0x, a0y, a1x, a1y);

        float f0, f1, f2, f3, f4, f5, f6, f7;
        unpack8(a0x, a0y, a1x, a1y, f0, f1, f2, f3, f4, f5, f6, f7);
        int c4 = lane * 4;
        acc[0][bl][c4+0] = f0;  acc[0][bl][c4+1] = f1;
        acc[0][bl][c4+2] = f2;  acc[0][bl][c4+3] = f3;
        acc[1][bl][c4+0] = f4;  acc[1][bl][c4+1] = f5;
        acc[1][bl][c4+2] = f6;  acc[1][bl][c4+3] = f7;
    }
    __syncthreads();

    // 256 output rows (b,c), 32 consecutive bins each -> coalesced stores
    #pragma unroll
    for (int r = warp; r < BATCH * CH; r += 8) {
        int b = r >> 7;
        int c = r & 127;
        float v = acc[b][lane][c];               // stride-129: conflict-free
        out[((size_t)(b * CH + c)) * NBIN + bin0 + lane] = v * sinv[lane];
    }
}

// ---------------------------------------------------------------------------
// gatherHot: 2048 warps steal global hot chunks (remainder beyond CAP of any
// bin). Accumulate in regs, then atomicAdd scaled partials into out.
// Runs AFTER gatherMain (launch order) so the plain stores land first.
// ---------------------------------------------------------------------------
__global__ void __launch_bounds__(256) gatherHot_kernel(float* __restrict__ out) {
    int warpg = blockIdx.x * 8 + (threadIdx.x >> 5);
    int lane  = threadIdx.x & 31;
    int nhc   = g_nhc;

    for (int cidx = warpg; cidx < nhc; cidx += HOTBLK * 8) {
        int bin = g_hc_bin[cidx];
        int beg = g_hc_beg[cidx];
        int end = beg + g_hc_len[cidx];
        int cnt = g_off[bin + 1] - g_off[bin];
        float inv = __fdiv_rn(1.0f, (float)cnt + 1e-5f);

        ull a0x = 0, a0y = 0, a1x = 0, a1y = 0;
        accum_run(beg, end, lane, a0x, a0y, a1x, a1y);

        float f0, f1, f2, f3, f4, f5, f6, f7;
        unpack8(a0x, a0y, a1x, a1y, f0, f1, f2, f3, f4, f5, f6, f7);
        int c4 = lane * 4;
        float* o0 = out + (size_t)c4 * NBIN + bin;             // batch 0
        float* o1 = out + ((size_t)CH + c4) * NBIN + bin;      // batch 1
        atomicAdd(o0 + 0*NBIN, f0 * inv);
        atomicAdd(o0 + 1*NBIN, f1 * inv);
        atomicAdd(o0 + 2*NBIN, f2 * inv);
        atomicAdd(o0 + 3*NBIN, f3 * inv);
        atomicAdd(o1 + 0*NBIN, f4 * inv);
        atomicAdd(o1 + 1*NBIN, f5 * inv);
        atomicAdd(o1 + 2*NBIN, f6 * inv);
        atomicAdd(o1 + 3*NBIN, f7 * inv);
    }
}

extern "C" void kernel_launch(void* const* d_in, const int* in_sizes, int n_in,
                              void* d_out, int out_size) {
    const float* feat  = (const float*)d_in[0];
    const float* depth = (const float*)d_in[1];
    const float* intr  = (const float*)d_in[2];
    const float* extr  = (const float*)d_in[3];
    const int*   img_h = (const int*)d_in[4];
    const int*   img_w = (const int*)d_in[5];
    float* out = (float*)d_out;

    pointA_kernel<<<PT_BLOCKS + TR_BLOCKS, 256>>>(feat, intr, extr, img_h, img_w);
    scan_kernel<<<64, 256>>>();
    fillB_kernel<<<FILL_BLOCKS + 1, 1024>>>(depth);
    gatherMain_kernel<<<NTILE, 256>>>(out);
    gatherHot_kernel<<<HOTBLK, 256>>>(out);
}

// round 11
// speedup vs baseline: 1.5778x; 1.5778x over previous
#include <cuda_runtime.h>

#define BATCH 2
#define NCAM  6
#define CH    128
#define IH    16
#define IW    44
#define ND    64
#define HW    (IH*IW)                 // 704
#define NPTS  (NCAM*ND*IH*IW)         // 270336 geometry points (batch-independent)
#define BEV_H 256
#define BEV_W 256
#define NBIN  (BEV_H*BEV_W)           // 65536
#define NTILE (NBIN/32)               // 2048
#define CAMSTRIDE (NCAM*ND*HW)        // depth elements per batch
#define B1OFF  (NCAM*HW*CH)           // featT offset of batch 1

#define PT_BLOCKS   (NPTS/256)        // 1056
#define TR_BLOCKS   ((CH/32)*(HW/32)*BATCH*NCAM)  // 1056
#define FILL_BLOCKS (NPTS/1024)       // 264

typedef unsigned long long ull;

// Static scratch (allocation-free per harness rules)
__device__ float g_featT[(size_t)BATCH*NCAM*HW*CH];  // feat channel-last: (bn, hw, c)
__device__ int   g_bin[NPTS];                        // bin index or -1
__device__ __align__(16) int g_cnt_i[NBIN];          // per-bin count (re-zeroed each run)
__device__ __align__(16) int g_off[NBIN+1];          // CSR offsets (exclusive)
__device__ __align__(16) int g_wptr[NBIN];           // write cursors for fill
__device__ int   g_bsum[64];
__device__ volatile int g_flag[64];                  // scan publish flags (re-zeroed each run)
__device__ int   g_sched[NTILE];                     // tile schedule, hot first
__device__ __align__(16) float4 g_list[NPTS];        // {fpix*CH as int, pad, d0, d1}

// ---------------------------------------------------------------------------
// In-block camera setup (geometry identical across batch; b=0 slices).
// ---------------------------------------------------------------------------
__device__ __forceinline__ void cam_setup(const float* __restrict__ intr,
                                          const float* __restrict__ extr,
                                          const int* __restrict__ pimg_h,
                                          const int* __restrict__ pimg_w,
                                          float* sKi, float* sRm, float* stv) {
    int n = threadIdx.x;
    if (n < NCAM) {
        float img_h = (float)pimg_h[0], img_w = (float)pimg_w[0];
        float sx = (float)IW / (img_w / 16.0f);
        float sy = (float)IH / (img_h / 16.0f);
        float rs0 = 16.0f / sx, rs1 = 16.0f / sy, rs2 = 1.0f;

        const float* Kp = intr + n*9;
        float a = Kp[0]*rs0, b = Kp[1]*rs0, c = Kp[2]*rs0;
        float d = Kp[3]*rs1, e = Kp[4]*rs1, f = Kp[5]*rs1;
        float g = Kp[6]*rs2, h = Kp[7]*rs2, i = Kp[8]*rs2;
        float A  = e*i - f*h;
        float Bc = -(d*i - f*g);
        float Cc = d*h - e*g;
        float det = a*A + b*Bc + c*Cc;
        float id = 1.0f / det;
        float* Ki = sKi + n*9;
        Ki[0] = A*id;             Ki[1] = (c*h - b*i)*id;  Ki[2] = (b*f - c*e)*id;
        Ki[3] = Bc*id;            Ki[4] = (a*i - c*g)*id;  Ki[5] = (c*d - a*f)*id;
        Ki[6] = Cc*id;            Ki[7] = (b*g - a*h)*id;  Ki[8] = (a*e - b*d)*id;

        const float* Ep = extr + n*16;
        #pragma unroll
        for (int r = 0; r < 3; r++) {
            #pragma unroll
            for (int cc = 0; cc < 3; cc++) sRm[n*9 + r*3+cc] = Ep[r*4+cc];
            stv[n*3 + r] = Ep[r*4+3];
        }
    }
}

// ---------------------------------------------------------------------------
// Fused kernel A: blocks [0, PT_BLOCKS) -> point geometry (bin + count);
// blocks [PT_BLOCKS, ...) -> feat transpose to channel-last.
// ---------------------------------------------------------------------------
__global__ void __launch_bounds__(256) pointA_kernel(
        const float* __restrict__ feat,
        const float* __restrict__ intr, const float* __restrict__ extr,
        const int* __restrict__ pimg_h, const int* __restrict__ pimg_w) {
    if (blockIdx.x < PT_BLOCKS) {
        __shared__ float sKi[NCAM*9], sRm[NCAM*9], stv[NCAM*3];
        cam_setup(intr, extr, pimg_h, pimg_w, sKi, sRm, stv);
        __syncthreads();

        int wp = blockIdx.x * 256 + threadIdx.x;
        int w   = wp % IW;  int t = wp / IW;
        int h   = t % IH;   t /= IH;
        int dci = t % ND;
        int n   = t / ND;

        float dd = 1.0f + (59.0f / 63.0f) * (float)dci;  // linspace(1,60,64)
        float ux = (float)w * dd;
        float vy = (float)h * dd;

        const float* Ki = sKi + n*9;
        float pcx = Ki[0]*ux + Ki[1]*vy + Ki[2]*dd;
        float pcy = Ki[3]*ux + Ki[4]*vy + Ki[5]*dd;
        float pcz = Ki[6]*ux + Ki[7]*vy + Ki[8]*dd;

        const float* Rm = sRm + n*9;
        const float* tv = stv + n*3;
        float px = Rm[0]*pcx + Rm[1]*pcy + Rm[2]*pcz + tv[0];
        float py = Rm[3]*pcx + Rm[4]*pcy + Rm[5]*pcz + tv[1];
        float pz = Rm[6]*pcx + Rm[7]*pcy + Rm[8]*pcz + tv[2];

        int xi = (int)__fdiv_rn(px - (-51.2f), 0.4f);
        int yi = (int)__fdiv_rn(py - (-51.2f), 0.4f);
        bool valid = (xi >= 0) & (xi < BEV_W) & (yi >= 0) & (yi < BEV_H)
                   & (pz >= -5.0f) & (pz <= 3.0f);

        int bin = yi * BEV_W + xi;
        g_bin[wp] = valid ? bin : -1;
        if (valid) atomicAdd(&g_cnt_i[bin], 1);
    } else {
        __shared__ float tile[32][33];
        int tb  = blockIdx.x - PT_BLOCKS;
        int c0  = (tb & 3) * 32;          // CH/32 = 4
        int hw0 = ((tb >> 2) % 22) * 32;  // HW/32 = 22
        int bn  = tb / 88;
        int x = threadIdx.x & 31, y = threadIdx.x >> 5;
        const float* src = feat + (size_t)bn * CH * HW;
        #pragma unroll
        for (int k = 0; k < 4; k++)
            tile[y + k*8][x] = src[(size_t)(c0 + y + k*8) * HW + hw0 + x];
        __syncthreads();
        #pragma unroll
        for (int k = 0; k < 4; k++)
            g_featT[((size_t)bn * HW + hw0 + y + k*8) * CH + c0 + x] = tile[x][y + k*8];
    }
}

// ---------------------------------------------------------------------------
// Single-kernel scan: 64 blocks x 256 threads x int4 (all co-resident).
// ---------------------------------------------------------------------------
__global__ void __launch_bounds__(256) scan_kernel() {
    __shared__ int wsum[8], wexcl[8], sexcl[64];
    int t   = threadIdx.x;
    int bid = blockIdx.x;
    int gb  = bid * 1024 + t * 4;
    int4 c = *(const int4*)&g_cnt_i[gb];
    int s = c.x + c.y + c.z + c.w;
    int lane = t & 31, wid = t >> 5;
    int incl = s;
    #pragma unroll
    for (int d = 1; d < 32; d <<= 1) {
        int v = __shfl_up_sync(0xffffffffu, incl, d);
        if (lane >= d) incl += v;
    }
    if (lane == 31) wsum[wid] = incl;
    __syncthreads();
    if (t < 8) {
        int v = wsum[t];
        int iv = v;
        #pragma unroll
        for (int d = 1; d < 8; d <<= 1) {
            int u = __shfl_up_sync(0xffu, iv, d);
            if (t >= d) iv += u;
        }
        wexcl[t] = iv - v;
    }
    __syncthreads();
    int excl = incl - s + wexcl[wid];
    if (t == 255) {
        g_bsum[bid] = excl + s;
        __threadfence();
        g_flag[bid] = 1;
    }

    if (t < 64) {
        while (g_flag[t] == 0) { }
    }
    __syncthreads();
    __threadfence();
    if (t < 64) {
        int v = g_bsum[t];
        int iv = v;
        int l = t & 31;
        #pragma unroll
        for (int d = 1; d < 32; d <<= 1) {
            int u = __shfl_up_sync(0xffffffffu, iv, d);
            if (l >= d) iv += u;
        }
        if (t == 31) wsum[0] = iv;
        __syncwarp();
        sexcl[t] = iv - v;
    }
    __syncthreads();
    int base = sexcl[bid] + ((bid >= 32) ? wsum[0] : 0);
    int4 o;
    o.x = base + excl; o.y = o.x + c.x; o.z = o.y + c.y; o.w = o.z + c.z;
    *(int4*)&g_off[gb]  = o;
    *(int4*)&g_wptr[gb] = o;
    if (bid == 63 && t == 255) g_off[NBIN] = o.w + c.w;
}

// ---------------------------------------------------------------------------
// Fused kernel B: fill fat list entries {fpix*CH, pad, d0, d1} with warp-
// aggregated cursor atomics; extra block builds the hot-first schedule and
// re-zeroes g_cnt_i / g_flag for replay (coalesced).
// ---------------------------------------------------------------------------
__global__ void __launch_bounds__(1024) fillB_kernel(const float* __restrict__ depth) {
    int t = threadIdx.x;
    if (blockIdx.x < FILL_BLOCKS) {
        int wp = blockIdx.x * 1024 + t;
        int bin = g_bin[wp];
        int lane = t & 31;

        // warp-aggregate cursor atomics by bin (hot bins: 32 atomics -> 1)
        unsigned mask = __match_any_sync(0xffffffffu, bin);
        if (bin >= 0) {
            int leader = __ffs(mask) - 1;
            int rank = __popc(mask & ((1u << lane) - 1u));
            int pos0 = 0;
            if (lane == leader) pos0 = atomicAdd(&g_wptr[bin], __popc(mask));
            pos0 = __shfl_sync(mask, pos0, leader);

            int w   = wp % IW;  int q = wp / IW;
            int h   = q % IH;   q /= IH;
            int dci = q % ND;
            int n   = q / ND;
            int hw  = h * IW + w;
            int dpo = (n * ND + dci) * HW + hw;

            float4 e;
            e.x = __int_as_float((n * HW + hw) * CH);
            e.y = 0.f;
            e.z = __ldg(&depth[dpo]);
            e.w = __ldg(&depth[CAMSTRIDE + dpo]);
            g_list[pos0 + rank] = e;
        }
    } else {
        // coalesced re-zero of counts + flags for next replay
        int4 z = {0, 0, 0, 0};
        #pragma unroll
        for (int j = 0; j < 16; j++)
            *(int4*)&g_cnt_i[(j * 1024 + t) * 4] = z;
        if (t < 64) *(int*)&g_flag[t] = 0;

        // hot-first schedule over 2048 tiles
        __shared__ int bcnt[8], bbase[8];
        if (t < 8) bcnt[t] = 0;
        __syncthreads();
        int ks[2];
        #pragma unroll
        for (int j = 0; j < 2; j++) {
            int tile = t + j * 1024;
            int cnt = g_off[tile*32 + 32] - g_off[tile*32];
            int k = cnt > 4096 ? 0 : cnt > 2048 ? 1 : cnt > 1024 ? 2 : cnt > 512 ? 3 :
                    cnt > 256  ? 4 : cnt > 128  ? 5 : cnt > 64   ? 6 : 7;
            ks[j] = k;
            atomicAdd(&bcnt[k], 1);
        }
        __syncthreads();
        if (t == 0) {
            int r = 0;
            #pragma unroll
            for (int k = 0; k < 8; k++) { bbase[k] = r; r += bcnt[k]; }
        }
        __syncthreads();
        #pragma unroll
        for (int j = 0; j < 2; j++) {
            int pos = atomicAdd(&bbase[ks[j]], 1);
            g_sched[pos] = t + j * 1024;
        }
    }
}

// ---------------------------------------------------------------------------
// Inner accumulate over [beg, end): LANE-PARALLEL list prefetch (one
// coalesced LDG.128 per 32 entries) + shuffle broadcast. Feat loads for
// successive entries are independent -> deep MLP without register blowup.
// ---------------------------------------------------------------------------
__device__ __forceinline__ void accum_run(int beg, int end, int lane,
        ull& a0x, ull& a0y, ull& a1x, ull& a1y) {
    for (int base = beg; base < end; base += 32) {
        int m = end - base;  if (m > 32) m = 32;
        float4 e = {0.f, 0.f, 0.f, 0.f};
        if (lane < m) e = g_list[base + lane];
        int fo = __float_as_int(e.x);

        #pragma unroll 4
        for (int j = 0; j < m; j++) {
            int   foff = __shfl_sync(0xffffffffu, fo,  j);
            float d0   = __shfl_sync(0xffffffffu, e.z, j);
            float d1   = __shfl_sync(0xffffffffu, e.w, j);
            ull d0p, d1p;
            asm("mov.b64 %0, {%1, %1};" : "=l"(d0p) : "f"(d0));
            asm("mov.b64 %0, {%1, %1};" : "=l"(d1p) : "f"(d1));
            ulonglong2 v0 = *((const ulonglong2*)(g_featT + foff) + lane);
            ulonglong2 v1 = *((const ulonglong2*)(g_featT + (B1OFF + foff)) + lane);
            asm("fma.rn.f32x2 %0, %1, %2, %0;" : "+l"(a0x) : "l"(v0.x), "l"(d0p));
            asm("fma.rn.f32x2 %0, %1, %2, %0;" : "+l"(a0y) : "l"(v0.y), "l"(d0p));
            asm("fma.rn.f32x2 %0, %1, %2, %0;" : "+l"(a1x) : "l"(v1.x), "l"(d1p));
            asm("fma.rn.f32x2 %0, %1, %2, %0;" : "+l"(a1y) : "l"(v1.y), "l"(d1p));
        }
    }
}

__device__ __forceinline__ void unpack8(ull a0x, ull a0y, ull a1x, ull a1y,
        float& f0, float& f1, float& f2, float& f3,
        float& f4, float& f5, float& f6, float& f7) {
    asm("mov.b64 {%0, %1}, %2;" : "=f"(f0), "=f"(f1) : "l"(a0x));
    asm("mov.b64 {%0, %1}, %2;" : "=f"(f2), "=f"(f3) : "l"(a0y));
    asm("mov.b64 {%0, %1}, %2;" : "=f"(f4), "=f"(f5) : "l"(a1x));
    asm("mov.b64 {%0, %1}, %2;" : "=f"(f6), "=f"(f7) : "l"(a1y));
}

// ---------------------------------------------------------------------------
// Gather: block = 32-bin tile (hot-first), 8 warps.
// Phase 1: warp owns 4 bins exclusively, first <=CAP points each, plain STS;
//          remainder chunks of hot bins pushed to an in-block queue.
// Phase 2: warps steal chunks, atomicAdd partials into smem (hot bins only).
// Epilogue: reciprocal * (bin,c)->(c,bin) transpose, coalesced STG.
// ---------------------------------------------------------------------------
#define CAP    32
#define CHUNK  64
#define MAXQ   1024
__global__ void __launch_bounds__(256) gather_kernel(float* __restrict__ out) {
    __shared__ float acc[BATCH][32][CH + 1];
    __shared__ float sinv[32];
    __shared__ short cq_bin[MAXQ];
    __shared__ int   cq_beg[MAXQ];
    __shared__ short cq_len[MAXQ];
    __shared__ int   sQn, sCtr;

    int tile = g_sched[blockIdx.x];
    int bin0 = tile * 32;
    int tid  = threadIdx.x;
    int warp = tid >> 5;
    int lane = tid & 31;

    if (tid == 0) { sQn = 0; sCtr = 0; }
    __syncthreads();

    // Phase 1: exclusive ownership, capped chains
    #pragma unroll
    for (int bl = warp; bl < 32; bl += 8) {
        int bin = bin0 + bl;
        int beg = g_off[bin];
        int end = g_off[bin + 1];
        int cnt = end - beg;
        if (lane == 0) sinv[bl] = __fdiv_rn(1.0f, (float)cnt + 1e-5f);

        int p1 = cnt < CAP ? cnt : CAP;
        ull a0x = 0, a0y = 0, a1x = 0, a1y = 0;
        accum_run(beg, beg + p1, lane, a0x, a0y, a1x, a1y);

        float f0, f1, f2, f3, f4, f5, f6, f7;
        unpack8(a0x, a0y, a1x, a1y, f0, f1, f2, f3, f4, f5, f6, f7);
        int c4 = lane * 4;
        acc[0][bl][c4+0] = f0;  acc[0][bl][c4+1] = f1;
        acc[0][bl][c4+2] = f2;  acc[0][bl][c4+3] = f3;
        acc[1][bl][c4+0] = f4;  acc[1][bl][c4+1] = f5;
        acc[1][bl][c4+2] = f6;  acc[1][bl][c4+3] = f7;

        if (cnt > CAP && lane == 0) {
            int rem = cnt - CAP;
            int nch = (rem + CHUNK - 1) / CHUNK;
            if (nch > 31) nch = 31;
            int cl = (rem + nch - 1) / nch;
            int qb = atomicAdd(&sQn, nch);
            int b0 = beg + p1;
            for (int j = 0; j < nch; j++) {
                cq_bin[qb + j] = (short)bl;
                cq_beg[qb + j] = b0 + j * cl;
                int l = rem - j * cl; if (l > cl) l = cl;
                cq_len[qb + j] = (short)l;
            }
        }
    }
    __syncthreads();

    // Phase 2: steal remainder chunks of hot bins
    int total = sQn;
    while (true) {
        int cidx;
        if (lane == 0) cidx = atomicAdd(&sCtr, 1);
        cidx = __shfl_sync(0xffffffffu, cidx, 0);
        if (cidx >= total) break;

        int bl  = cq_bin[cidx];
        int beg = cq_beg[cidx];
        int end = beg + cq_len[cidx];
        ull a0x = 0, a0y = 0, a1x = 0, a1y = 0;
        accum_run(beg, end, lane, a0x, a0y, a1x, a1y);

        float f0, f1, f2, f3, f4, f5, f6, f7;
        unpack8(a0x, a0y, a1x, a1y, f0, f1, f2, f3, f4, f5, f6, f7);
        int c4 = lane * 4;
        atomicAdd(&acc[0][bl][c4+0], f0);  atomicAdd(&acc[0][bl][c4+1], f1);
        atomicAdd(&acc[0][bl][c4+2], f2);  atomicAdd(&acc[0][bl][c4+3], f3);
        atomicAdd(&acc[1][bl][c4+0], f4);  atomicAdd(&acc[1][bl][c4+1], f5);
        atomicAdd(&acc[1][bl][c4+2], f6);  atomicAdd(&acc[1][bl][c4+3], f7);
    }
    __syncthreads();

    // Epilogue: 256 output rows (b,c), 32 consecutive bins each -> coalesced
    #pragma unroll
    for (int r = warp; r < BATCH * CH; r += 8) {
        int b = r >> 7;
        int c = r & 127;
        float v = acc[b][lane][c];               // stride-129: conflict-free
        out[((size_t)(b * CH + c)) * NBIN + bin0 + lane] = v * sinv[lane];
    }
}

extern "C" void kernel_launch(void* const* d_in, const int* in_sizes, int n_in,
                              void* d_out, int out_size) {
    const float* feat  = (const float*)d_in[0];
    const float* depth = (const float*)d_in[1];
    const float* intr  = (const float*)d_in[2];
    const float* extr  = (const float*)d_in[3];
    const int*   img_h = (const int*)d_in[4];
    const int*   img_w = (const int*)d_in[5];
    float* out = (float*)d_out;

    pointA_kernel<<<PT_BLOCKS + TR_BLOCKS, 256>>>(feat, intr, extr, img_h, img_w);
    scan_kernel<<<64, 256>>>();
    fillB_kernel<<<FILL_BLOCKS + 1, 1024>>>(depth);
    gather_kernel<<<NTILE, 256>>>(out);
}